// round 13
// baseline (speedup 1.0000x reference)
#include <cuda_runtime.h>
#include <cuda_fp16.h>
#include <cstdint>

#define DEVI __device__ __forceinline__

namespace cfg {
constexpr int NB = 16;
constexpr int NS = 512;
constexpr int ND = 1024;
constexpr int NH = 16;
constexpr int NF = 4096;
constexpr int NL = 4;
constexpr int NM = NB * NS;
constexpr int HD = ND / NH;
}

// ---------------------------------------------------------------------------
// Scratch
// ---------------------------------------------------------------------------
__device__ float  g_t0 [cfg::NM * cfg::ND];
__device__ float  g_x1 [cfg::NM * cfg::ND];
__device__ float  g_bqkv[cfg::NL * 3 * cfg::ND];
__device__ __half h_x  [cfg::NM * cfg::ND];
__device__ __half h_x1b[cfg::NM * cfg::ND];
__device__ __half h_qkv[(size_t)cfg::NM * 3 * cfg::ND];
__device__ __half h_vt [cfg::NB * cfg::NH * cfg::HD * cfg::NS];
__device__ __half h_ctx[cfg::NM * cfg::ND];
__device__ __half h_hh [(size_t)cfg::NM * cfg::NF];
__device__ __half h_wt [(size_t)48 * 1024 * 1024];

// wt layout (halves): per-layer QKV interleaved [3072,1024], then P, W1t, W2t
constexpr long long WT_QKV = 0;                      // 4 layers x 3 x 1M
constexpr long long WT_P   = 12LL * 1024 * 1024;
constexpr long long WT_1   = 16LL * 1024 * 1024;
constexpr long long WT_2   = 32LL * 1024 * 1024;

// ---------------------------------------------------------------------------
// PTX helpers
// ---------------------------------------------------------------------------
DEVI uint32_t s2u(const void* p) {
    uint32_t a;
    asm("{ .reg .u64 t; cvta.to.shared.u64 t, %1; cvt.u32.u64 %0, t; }"
        : "=r"(a) : "l"(p));
    return a;
}

DEVI void cp16(uint32_t dst, const void* src) {
    asm volatile("cp.async.cg.shared.global [%0], [%1], 16;"
                 :: "r"(dst), "l"(src));
}
#define CP_COMMIT() asm volatile("cp.async.commit_group;" ::: "memory")
#define CP_WAIT1()  asm volatile("cp.async.wait_group 1;" ::: "memory")

DEVI void ldsm4(uint32_t r[4], uint32_t addr) {
    asm volatile("ldmatrix.sync.aligned.m8n8.x4.shared.b16 {%0,%1,%2,%3}, [%4];"
                 : "=r"(r[0]), "=r"(r[1]), "=r"(r[2]), "=r"(r[3]) : "r"(addr));
}

DEVI void mma_h(float c[4], const uint32_t a[4], const uint32_t b[2]) {
    asm volatile(
        "mma.sync.aligned.m16n8k16.row.col.f32.f16.f16.f32 "
        "{%0,%1,%2,%3}, {%4,%5,%6,%7}, {%8,%9}, {%0,%1,%2,%3};\n"
        : "+f"(c[0]), "+f"(c[1]), "+f"(c[2]), "+f"(c[3])
        : "r"(a[0]), "r"(a[1]), "r"(a[2]), "r"(a[3]), "r"(b[0]), "r"(b[1]));
}

DEVI uint32_t packh2(float a, float b) {
    __half2 h = __floats2half2_rn(a, b);
    return *reinterpret_cast<uint32_t*>(&h);
}

// ---------------------------------------------------------------------------
// fp16 GEMM: C[M,N] = act( A[M,K] @ Bt[N,K]^T + bias + resid )
// BM=128, BN=128, BK=64, 3-stage cp.async pipeline with EARLY prefetch
// (issue t+2 right after the stage barrier, before compute of t).
// 128 threads = 4 warps, warp tile 64x64 (2x2 grid).
// ---------------------------------------------------------------------------
constexpr int HG_AB  = 128 * 128;          // 16 KB per A stage
constexpr int HG_STG = 2 * HG_AB;          // 32 KB per stage (A + B)
constexpr int HG_SMEM = 3 * HG_STG;        // 96 KB

template <bool RELU>
__global__ void __launch_bounds__(128)
hgemm(const __half* __restrict__ A, const __half* __restrict__ Bt,
      const float* __restrict__ bias, const float* __restrict__ resid,
      float* __restrict__ Cf, __half* __restrict__ Ch, int K, int N)
{
    extern __shared__ __align__(16) char smem[];
    const uint32_t dsb = s2u(smem);

    const int m0 = blockIdx.y * 128;
    const int n0 = blockIdx.x * 128;
    const int tid = threadIdx.x, lane = tid & 31, warp = tid >> 5;
    const int wm = (warp >> 1) * 64;
    const int wn = (warp & 1) * 64;

    const __half* ga = A  + (long long)m0 * K;
    const __half* gb = Bt + (long long)n0 * K;

    auto issue = [&](int t, int st) {
        const uint32_t sa = dsb + st * HG_STG;
        const uint32_t sb = sa + HG_AB;
        const __half* pa = ga + t * 64;
        const __half* pb = gb + t * 64;
#pragma unroll
        for (int i = 0; i < 8; i++) {
            const int idx = tid + i * 128;
            const int r = idx >> 3, c = idx & 7;
            const uint32_t sw = (uint32_t)(r * 128 + ((c ^ (r & 7)) << 4));
            cp16(sa + sw, pa + (long long)r * K + c * 8);
            cp16(sb + sw, pb + (long long)r * K + c * 8);
        }
    };

    float acc[4][8][4];
#pragma unroll
    for (int mt = 0; mt < 4; mt++)
#pragma unroll
        for (int nt = 0; nt < 8; nt++)
#pragma unroll
            for (int i = 0; i < 4; i++) acc[mt][nt][i] = 0.f;

    const int T = K / 64;
    issue(0, 0); CP_COMMIT();
    issue(1, 1); CP_COMMIT();

    const int arow = lane & 15;
    const int akh  = lane >> 4;
    const int brow = ((lane >> 4) << 3) + (lane & 7);
    const int bkh  = (lane >> 3) & 1;

    for (int t = 0; t < T; t++) {
        CP_WAIT1();
        __syncthreads();
        // EARLY prefetch: stage (t+2)%3 held tile t-1, fully consumed before
        // the barrier above -> safe to overwrite now. Gives the cp.async
        // group ~2 compute iterations of latency cover instead of ~1.
        const int tn = t + 2;
        if (tn < T) issue(tn, tn % 3);
        CP_COMMIT();

        const uint32_t sa = dsb + (t % 3) * HG_STG;
        const uint32_t sb = sa + HG_AB;
#pragma unroll
        for (int kk = 0; kk < 4; kk++) {          // 4 x k16 per BK=64
            uint32_t af[4][4];
#pragma unroll
            for (int mt = 0; mt < 4; mt++) {
                const int r = wm + mt * 16 + arow;
                const int c = kk * 2 + akh;
                ldsm4(af[mt], sa + r * 128 + ((c ^ (r & 7)) << 4));
            }
            uint32_t bf[8][2];
#pragma unroll
            for (int bt = 0; bt < 4; bt++) {
                const int r = wn + bt * 16 + brow;
                const int c = kk * 2 + bkh;
                uint32_t qq[4];
                ldsm4(qq, sb + r * 128 + ((c ^ (r & 7)) << 4));
                bf[2 * bt][0] = qq[0]; bf[2 * bt][1] = qq[1];
                bf[2 * bt + 1][0] = qq[2]; bf[2 * bt + 1][1] = qq[3];
            }
#pragma unroll
            for (int mt = 0; mt < 4; mt++)
#pragma unroll
                for (int nt = 0; nt < 8; nt++)
                    mma_h(acc[mt][nt], af[mt], bf[nt]);
        }
    }

#pragma unroll
    for (int mt = 0; mt < 4; mt++) {
#pragma unroll
        for (int nt = 0; nt < 8; nt++) {
            const int col = n0 + wn + nt * 8 + 2 * (lane & 3);
#pragma unroll
            for (int h = 0; h < 2; h++) {
                const int row = m0 + wm + mt * 16 + (lane >> 2) + h * 8;
                float v0 = acc[mt][nt][2 * h];
                float v1 = acc[mt][nt][2 * h + 1];
                if (bias)  { v0 += bias[col]; v1 += bias[col + 1]; }
                if (resid) {
                    const float* rp = resid + (long long)row * N + col;
                    v0 += rp[0]; v1 += rp[1];
                }
                if (RELU) { v0 = fmaxf(v0, 0.f); v1 = fmaxf(v1, 0.f); }
                const long long o = (long long)row * N + col;
                if (Cf) *reinterpret_cast<float2*>(Cf + o) = make_float2(v0, v1);
                if (Ch) *reinterpret_cast<__half2*>(Ch + o) = __floats2half2_rn(v0, v1);
            }
        }
    }
}

// ---------------------------------------------------------------------------
// Fused flash attention over fused QKV buffer [B*S, 3072].
//   q cols [0,1024), k cols [1024,2048); head h at +h*64.
//   vt: [bh][64][512]; ctx out: [B*S, 1024].
//   Early prefetch as in hgemm.
// ---------------------------------------------------------------------------
constexpr int FA_QB  = 16384;
constexpr int FA_KB  = 16384;
constexpr int FA_VB  = 16384;
constexpr int FA_KVB = FA_KB + FA_VB;
constexpr int FA_SMEM = FA_QB + 3 * FA_KVB;   // 112 KB

__global__ void __launch_bounds__(256)
flash_attn(const __half* __restrict__ qkv, const __half* __restrict__ vt,
           __half* __restrict__ ctx)
{
    extern __shared__ __align__(16) char smem[];
    const uint32_t sQ = s2u(smem);
    const uint32_t sKV0 = sQ + FA_QB;

    const int bh = blockIdx.y, b = bh >> 4, h = bh & 15;
    const int q0 = blockIdx.x * 128;
    const int tid = threadIdx.x, lane = tid & 31, warp = tid >> 5;

    const __half* gq = qkv + ((long long)(b * 512 + q0)) * 3072 + h * 64;
    const __half* gk = qkv + ((long long)(b * 512)) * 3072 + 1024 + h * 64;
    const __half* gv = vt + (long long)bh * 64 * 512;

#pragma unroll
    for (int i = 0; i < 4; i++) {
        const int idx = tid + i * 256;
        const int r = idx >> 3, c = idx & 7;
        cp16(sQ + r * 128 + ((c ^ (r & 7)) << 4), gq + (long long)r * 3072 + c * 8);
    }
    auto ldKV = [&](int t, int st) {
        const uint32_t sk = sKV0 + st * FA_KVB;
        const uint32_t sv = sk + FA_KB;
        const __half* pk = gk + (long long)t * 128 * 3072;
#pragma unroll
        for (int i = 0; i < 4; i++) {
            const int idx = tid + i * 256;
            const int r = idx >> 3, c = idx & 7;
            cp16(sk + r * 128 + ((c ^ (r & 7)) << 4), pk + (long long)r * 3072 + c * 8);
        }
#pragma unroll
        for (int i = 0; i < 4; i++) {
            const int idx = tid + i * 256;
            const int r = idx >> 4, c = idx & 15;
            cp16(sv + r * 256 + ((c ^ (r & 7)) << 4),
                 gv + (long long)r * 512 + t * 128 + c * 8);
        }
    };
    ldKV(0, 0); CP_COMMIT();
    ldKV(1, 1); CP_COMMIT();

    // scale folds 1/sqrt(d) and log2(e): softmax in exp2 domain (fp32)
    const float SC = 0.125f * 1.44269504f;

    float m0v = -1e30f, m1v = -1e30f, l0 = 0.f, l1 = 0.f;
    float oa[8][4];
#pragma unroll
    for (int nt = 0; nt < 8; nt++)
#pragma unroll
        for (int i = 0; i < 4; i++) oa[nt][i] = 0.f;

    const int arow = lane & 15, akh = lane >> 4;
    const int brow = ((lane >> 4) << 3) + (lane & 7), bkh = (lane >> 3) & 1;

    uint32_t afq[4][4];      // Q fragments, loaded once at t==0

    for (int t = 0; t < 4; t++) {
        CP_WAIT1();
        __syncthreads();
        const int tn = t + 2;
        if (tn < 4) ldKV(tn, tn % 3);
        CP_COMMIT();

        const uint32_t sk = sKV0 + (t % 3) * FA_KVB;
        const uint32_t sv = sk + FA_KB;

        if (t == 0) {
#pragma unroll
            for (int kk = 0; kk < 4; kk++) {
                const int r = warp * 16 + arow;
                const int c = kk * 2 + akh;
                ldsm4(afq[kk], sQ + r * 128 + ((c ^ (r & 7)) << 4));
            }
        }

        // ---- S = Q @ K^T (warp: 16 q-rows x 128 kv-cols) ----
        float sacc[16][4];
#pragma unroll
        for (int nt = 0; nt < 16; nt++)
#pragma unroll
            for (int i = 0; i < 4; i++) sacc[nt][i] = 0.f;
#pragma unroll
        for (int kk = 0; kk < 4; kk++) {
            uint32_t bf[16][2];
#pragma unroll
            for (int bt = 0; bt < 8; bt++) {
                const int r = bt * 16 + brow;
                const int c = kk * 2 + bkh;
                uint32_t qq[4];
                ldsm4(qq, sk + r * 128 + ((c ^ (r & 7)) << 4));
                bf[2 * bt][0] = qq[0]; bf[2 * bt][1] = qq[1];
                bf[2 * bt + 1][0] = qq[2]; bf[2 * bt + 1][1] = qq[3];
            }
#pragma unroll
            for (int nt = 0; nt < 16; nt++)
                mma_h(sacc[nt], afq[kk], bf[nt]);
        }

        // ---- online softmax, exp2 domain (rows lane>>2 and +8) ----
        float mx0 = -1e30f, mx1 = -1e30f;
#pragma unroll
        for (int nt = 0; nt < 16; nt++) {
            sacc[nt][0] *= SC; sacc[nt][1] *= SC;
            sacc[nt][2] *= SC; sacc[nt][3] *= SC;
            mx0 = fmaxf(mx0, fmaxf(sacc[nt][0], sacc[nt][1]));
            mx1 = fmaxf(mx1, fmaxf(sacc[nt][2], sacc[nt][3]));
        }
        mx0 = fmaxf(mx0, __shfl_xor_sync(0xffffffffu, mx0, 1));
        mx0 = fmaxf(mx0, __shfl_xor_sync(0xffffffffu, mx0, 2));
        mx1 = fmaxf(mx1, __shfl_xor_sync(0xffffffffu, mx1, 1));
        mx1 = fmaxf(mx1, __shfl_xor_sync(0xffffffffu, mx1, 2));
        const float mn0 = fmaxf(m0v, mx0), mn1 = fmaxf(m1v, mx1);
        const float al0 = exp2f(m0v - mn0), al1 = exp2f(m1v - mn1);

        uint32_t ph[16][2];
        float s0 = 0.f, s1 = 0.f;
#pragma unroll
        for (int nt = 0; nt < 16; nt++) {
            const float e0 = exp2f(sacc[nt][0] - mn0);
            const float e1 = exp2f(sacc[nt][1] - mn0);
            const float e2 = exp2f(sacc[nt][2] - mn1);
            const float e3 = exp2f(sacc[nt][3] - mn1);
            s0 += e0 + e1; s1 += e2 + e3;
            ph[nt][0] = packh2(e0, e1);
            ph[nt][1] = packh2(e2, e3);
        }
        s0 += __shfl_xor_sync(0xffffffffu, s0, 1);
        s0 += __shfl_xor_sync(0xffffffffu, s0, 2);
        s1 += __shfl_xor_sync(0xffffffffu, s1, 1);
        s1 += __shfl_xor_sync(0xffffffffu, s1, 2);
        l0 = al0 * l0 + s0; l1 = al1 * l1 + s1;
#pragma unroll
        for (int nt = 0; nt < 8; nt++) {
            oa[nt][0] *= al0; oa[nt][1] *= al0;
            oa[nt][2] *= al1; oa[nt][3] *= al1;
        }
        m0v = mn0; m1v = mn1;

        // ---- O += P @ V^T-tile ----
#pragma unroll
        for (int kc = 0; kc < 8; kc++) {
            uint32_t a[4] = {ph[2 * kc][0], ph[2 * kc][1],
                             ph[2 * kc + 1][0], ph[2 * kc + 1][1]};
            uint32_t bv[8][2];
#pragma unroll
            for (int bt = 0; bt < 4; bt++) {
                const int r = bt * 16 + brow;
                const int c = kc * 2 + bkh;
                uint32_t qq[4];
                ldsm4(qq, sv + r * 256 + ((c ^ (r & 7)) << 4));
                bv[2 * bt][0] = qq[0]; bv[2 * bt][1] = qq[1];
                bv[2 * bt + 1][0] = qq[2]; bv[2 * bt + 1][1] = qq[3];
            }
#pragma unroll
            for (int nt = 0; nt < 8; nt++)
                mma_h(oa[nt], a, bv[nt]);
        }
    }

    const float r0 = 1.f / l0, r1 = 1.f / l1;
    const int row_lo = b * 512 + q0 + warp * 16 + (lane >> 2);
    __half* c0p = ctx + (long long)row_lo * 1024 + h * 64 + 2 * (lane & 3);
    __half* c1p = c0p + 8 * 1024;
#pragma unroll
    for (int nt = 0; nt < 8; nt++) {
        *reinterpret_cast<__half2*>(c0p + nt * 8) =
            __floats2half2_rn(oa[nt][0] * r0, oa[nt][1] * r0);
        *reinterpret_cast<__half2*>(c1p + nt * 8) =
            __floats2half2_rn(oa[nt][2] * r1, oa[nt][3] * r1);
    }
}

// ---------------------------------------------------------------------------
// Square weights -> f16 transposed. z = m*4 + l; m in {0,1,2}=QKV interleaved,
// m=3 -> Wp region.
// ---------------------------------------------------------------------------
__global__ void __launch_bounds__(256)
transpose_sq(const float* __restrict__ a0, const float* __restrict__ a1,
             const float* __restrict__ a2, const float* __restrict__ a3,
             __half* __restrict__ wt)
{
    __shared__ float tile[32][33];
    const int m = blockIdx.z >> 2, l = blockIdx.z & 3;
    const float* src = (m == 0 ? a0 : m == 1 ? a1 : m == 2 ? a2 : a3)
                       + (long long)l * 1048576;
    __half* dst = (m < 3)
        ? wt + ((long long)l * 3 + m) * 1048576
        : wt + WT_P + (long long)l * 1048576;
    const int c0 = blockIdx.x * 32, r0 = blockIdx.y * 32;
    const int tx = threadIdx.x & 31, ty = threadIdx.x >> 5;
#pragma unroll
    for (int i = 0; i < 4; i++)
        tile[ty + 8 * i][tx] = src[(long long)(r0 + ty + 8 * i) * 1024 + c0 + tx];
    __syncthreads();
#pragma unroll
    for (int i = 0; i < 4; i++)
        dst[(long long)(c0 + ty + 8 * i) * 1024 + r0 + tx] =
            __float2half(tile[tx][ty + 8 * i]);
}

// ---------------------------------------------------------------------------
// Generic weight transpose [R,C] f32 -> [C,R] f16 (grid.z = layer)
// ---------------------------------------------------------------------------
__global__ void __launch_bounds__(256)
transpose_wh(const float* __restrict__ src, __half* __restrict__ dst, int R, int Cn)
{
    __shared__ float tile[32][33];
    const long long msz = (long long)R * Cn;
    src += blockIdx.z * msz; dst += blockIdx.z * msz;
    const int c0 = blockIdx.x * 32, r0 = blockIdx.y * 32;
    const int tx = threadIdx.x & 31, ty = threadIdx.x >> 5;
#pragma unroll
    for (int i = 0; i < 4; i++)
        tile[ty + 8 * i][tx] = src[(long long)(r0 + ty + 8 * i) * Cn + c0 + tx];
    __syncthreads();
#pragma unroll
    for (int i = 0; i < 4; i++)
        dst[(long long)(c0 + ty + 8 * i) * R + r0 + tx] =
            __float2half(tile[tx][ty + 8 * i]);
}

// ---------------------------------------------------------------------------
// Bias concat: bqkv[l][3072] = [bq | bk | bv]
// ---------------------------------------------------------------------------
__global__ void __launch_bounds__(256)
concat_bias(const float* __restrict__ bq, const float* __restrict__ bk,
            const float* __restrict__ bv, float* __restrict__ out)
{
    const int i = blockIdx.x * 256 + threadIdx.x;      // 0 .. 12287
    const int l = i / 3072, j = i % 3072;
    float v;
    if (j < 1024)       v = bq[l * 1024 + j];
    else if (j < 2048)  v = bk[l * 1024 + j - 1024];
    else                v = bv[l * 1024 + j - 2048];
    out[i] = v;
}

// ---------------------------------------------------------------------------
// Per-head V transpose from fused qkv: vt[bh][64][512]
// ---------------------------------------------------------------------------
__global__ void __launch_bounds__(256)
transpose_v(const __half* __restrict__ qkv, __half* __restrict__ vt)
{
    __shared__ __half tile[64][65];
    const int s0 = blockIdx.x * 64;
    const int bh = blockIdx.y;
    const int b = bh >> 4, h = bh & 15;
    const int tid = threadIdx.x;
    const __half* v = qkv + 2048 + h * 64;
#pragma unroll
    for (int i = 0; i < 16; i++) {
        const int lin = tid + i * 256;
        const int r = lin >> 6, c = lin & 63;
        tile[c][r] = v[((long long)(b * 512 + s0 + r)) * 3072 + c];
    }
    __syncthreads();
    __half* dst = vt + (long long)bh * 64 * 512;
#pragma unroll
    for (int i = 0; i < 16; i++) {
        const int lin = tid + i * 256;
        const int r = lin >> 6, c = lin & 63;
        dst[(long long)r * 512 + s0 + c] = tile[r][c];
    }
}

// ---------------------------------------------------------------------------
// f32 copy + f16 convert
// ---------------------------------------------------------------------------
__global__ void __launch_bounds__(256)
cvtcopy(const float* __restrict__ src, float* __restrict__ dst,
        __half* __restrict__ dsth, int n)
{
    const int i = (blockIdx.x * 256 + threadIdx.x) * 4;
    if (i < n) {
        float4 v = *reinterpret_cast<const float4*>(src + i);
        *reinterpret_cast<float4*>(dst + i) = v;
        *reinterpret_cast<__half2*>(dsth + i)     = __floats2half2_rn(v.x, v.y);
        *reinterpret_cast<__half2*>(dsth + i + 2) = __floats2half2_rn(v.z, v.w);
    }
}

// ---------------------------------------------------------------------------
// LayerNorm over D=1024, dual f32 + f16 outputs, float4 access.
// ---------------------------------------------------------------------------
__global__ void __launch_bounds__(256)
ln1024(const float* __restrict__ x, const float* __restrict__ g,
       const float* __restrict__ be, float* __restrict__ out,
       __half* __restrict__ out16)
{
    __shared__ float red[16];
    const int row = blockIdx.x, tid = threadIdx.x;
    const float4 v4 = *reinterpret_cast<const float4*>(x + (long long)row * 1024 + tid * 4);
    float s  = v4.x + v4.y + v4.z + v4.w;
    float sq = v4.x * v4.x + v4.y * v4.y + v4.z * v4.z + v4.w * v4.w;
    const int lane = tid & 31, w = tid >> 5;
#pragma unroll
    for (int o = 16; o > 0; o >>= 1) {
        s  += __shfl_xor_sync(0xffffffffu, s, o);
        sq += __shfl_xor_sync(0xffffffffu, sq, o);
    }
    if (lane == 0) { red[w] = s; red[8 + w] = sq; }
    __syncthreads();
    s = 0.f; sq = 0.f;
#pragma unroll
    for (int i = 0; i < 8; i++) { s += red[i]; sq += red[8 + i]; }
    const float mean = s * (1.f / 1024.f);
    const float var  = sq * (1.f / 1024.f) - mean * mean;
    const float inv  = rsqrtf(var + 1e-6f);
    const float4 g4  = *reinterpret_cast<const float4*>(g  + tid * 4);
    const float4 b4  = *reinterpret_cast<const float4*>(be + tid * 4);
    float4 o4;
    o4.x = (v4.x - mean) * inv * g4.x + b4.x;
    o4.y = (v4.y - mean) * inv * g4.y + b4.y;
    o4.z = (v4.z - mean) * inv * g4.z + b4.z;
    o4.w = (v4.w - mean) * inv * g4.w + b4.w;
    *reinterpret_cast<float4*>(out + (long long)row * 1024 + tid * 4) = o4;
    __half* o16 = out16 + (long long)row * 1024 + tid * 4;
    *reinterpret_cast<__half2*>(o16)     = __floats2half2_rn(o4.x, o4.y);
    *reinterpret_cast<__half2*>(o16 + 2) = __floats2half2_rn(o4.z, o4.w);
}

// ---------------------------------------------------------------------------
// Driver
// ---------------------------------------------------------------------------
extern "C" void kernel_launch(void* const* d_in, const int* in_sizes, int n_in,
                              void* d_out, int out_size)
{
    using namespace cfg;
    (void)in_sizes; (void)n_in; (void)out_size;

    const float* hs  = (const float*)d_in[0];
    const float* Wq  = (const float*)d_in[1];
    const float* bq  = (const float*)d_in[2];
    const float* Wk  = (const float*)d_in[3];
    const float* bk  = (const float*)d_in[4];
    const float* Wv  = (const float*)d_in[5];
    const float* bv  = (const float*)d_in[6];
    const float* Wp  = (const float*)d_in[7];
    const float* bp  = (const float*)d_in[8];
    const float* g1  = (const float*)d_in[9];
    const float* be1 = (const float*)d_in[10];
    const float* W1  = (const float*)d_in[11];
    const float* b1  = (const float*)d_in[12];
    const float* W2  = (const float*)d_in[13];
    const float* b2  = (const float*)d_in[14];
    const float* g2  = (const float*)d_in[15];
    const float* be2 = (const float*)d_in[16];

    float* x = (float*)d_out;

    float *t0, *x1, *bqkv;
    __half *x16, *x116, *qkv16, *vt, *ctx16, *hh16, *wt;
    cudaGetSymbolAddress((void**)&t0,    g_t0);
    cudaGetSymbolAddress((void**)&x1,    g_x1);
    cudaGetSymbolAddress((void**)&bqkv,  g_bqkv);
    cudaGetSymbolAddress((void**)&x16,   h_x);
    cudaGetSymbolAddress((void**)&x116,  h_x1b);
    cudaGetSymbolAddress((void**)&qkv16, h_qkv);
    cudaGetSymbolAddress((void**)&vt,    h_vt);
    cudaGetSymbolAddress((void**)&ctx16, h_ctx);
    cudaGetSymbolAddress((void**)&hh16,  h_hh);
    cudaGetSymbolAddress((void**)&wt,    h_wt);

    cudaFuncSetAttribute(hgemm<false>, cudaFuncAttributeMaxDynamicSharedMemorySize, HG_SMEM);
    cudaFuncSetAttribute(hgemm<true>,  cudaFuncAttributeMaxDynamicSharedMemorySize, HG_SMEM);
    cudaFuncSetAttribute(flash_attn,   cudaFuncAttributeMaxDynamicSharedMemorySize, FA_SMEM);

    const dim3 blk(256);
    const dim3 blkg(128);

    // 3 prep launches -> first (fused QKV) hgemm is launch index 3, the
    // slot ncu captures.
    transpose_sq<<<dim3(32, 32, 16), blk>>>(Wq, Wk, Wv, Wp, wt);
    concat_bias<<<48, blk>>>(bq, bk, bv, bqkv);
    cvtcopy<<<NM * ND / 1024, blk>>>(hs, x, x16, NM * ND);

    bool w12_done = false;

    for (int l = 0; l < NL; l++) {
        const __half* wqkv = wt + WT_QKV + (long long)l * 3 * 1048576;
        const __half* wtp  = wt + WT_P   + (long long)l * ND * ND;
        const __half* wt1  = wt + WT_1   + (long long)l * ND * NF;
        const __half* wt2  = wt + WT_2   + (long long)l * NF * ND;
        const float* bqkvl = bqkv + (long long)l * 3 * ND;
        const float* bpl = bp + (long long)l * ND;
        const float* b1l = b1 + (long long)l * NF;
        const float* b2l = b2 + (long long)l * ND;
        const float* g1l = g1 + (long long)l * ND;
        const float* e1l = be1 + (long long)l * ND;
        const float* g2l = g2 + (long long)l * ND;
        const float* e2l = be2 + (long long)l * ND;

        // fused QKV: [8192, 3072]
        hgemm<false><<<dim3(24, 64), blkg, HG_SMEM>>>(
            x16, wqkv, bqkvl, nullptr, nullptr, qkv16, ND, 3 * ND);

        if (!w12_done) {
            transpose_wh<<<dim3(128, 32, NL), blk>>>(W1, wt + WT_1, ND, NF);
            transpose_wh<<<dim3(32, 128, NL), blk>>>(W2, wt + WT_2, NF, ND);
            w12_done = true;
        }

        transpose_v<<<dim3(8, NB * NH), blk>>>(qkv16, vt);

        flash_attn<<<dim3(4, NB * NH), blk, FA_SMEM>>>(qkv16, vt, ctx16);

        hgemm<false><<<dim3(8, 64), blkg, HG_SMEM>>>(
            ctx16, wtp, bpl, x, t0, nullptr, ND, ND);

        ln1024<<<NM, blk>>>(t0, g1l, e1l, x1, x116);

        hgemm<true><<<dim3(32, 64), blkg, HG_SMEM>>>(
            x116, wt1, b1l, nullptr, nullptr, hh16, ND, NF);

        hgemm<false><<<dim3(8, 64), blkg, HG_SMEM>>>(
            hh16, wt2, b2l, x1, t0, nullptr, NF, ND);

        ln1024<<<NM, blk>>>(t0, g2l, e2l, x, x16);
    }
}

// round 14
// speedup vs baseline: 1.0670x; 1.0670x over previous
#include <cuda_runtime.h>
#include <cuda_fp16.h>
#include <cstdint>

#define DEVI __device__ __forceinline__

namespace cfg {
constexpr int NB = 16;
constexpr int NS = 512;
constexpr int ND = 1024;
constexpr int NH = 16;
constexpr int NF = 4096;
constexpr int NL = 4;
constexpr int NM = NB * NS;
constexpr int HD = ND / NH;
}

// ---------------------------------------------------------------------------
// Scratch
// ---------------------------------------------------------------------------
__device__ float  g_t0 [cfg::NM * cfg::ND];
__device__ float  g_x1 [cfg::NM * cfg::ND];
__device__ float  g_bqkv[cfg::NL * 3 * cfg::ND];
__device__ __half h_x  [cfg::NM * cfg::ND];
__device__ __half h_x1b[cfg::NM * cfg::ND];
__device__ __half h_qkv[(size_t)cfg::NM * 3 * cfg::ND];
__device__ __half h_vt [cfg::NB * cfg::NH * cfg::HD * cfg::NS];
__device__ __half h_ctx[cfg::NM * cfg::ND];
__device__ __half h_hh [(size_t)cfg::NM * cfg::NF];
__device__ __half h_wt [(size_t)48 * 1024 * 1024];

// wt layout (halves): per-layer QKV interleaved [3072,1024], then P, W1t, W2t
constexpr long long WT_QKV = 0;                      // 4 layers x 3 x 1M
constexpr long long WT_P   = 12LL * 1024 * 1024;
constexpr long long WT_1   = 16LL * 1024 * 1024;
constexpr long long WT_2   = 32LL * 1024 * 1024;

// ---------------------------------------------------------------------------
// PTX helpers
// ---------------------------------------------------------------------------
DEVI uint32_t s2u(const void* p) {
    uint32_t a;
    asm("{ .reg .u64 t; cvta.to.shared.u64 t, %1; cvt.u32.u64 %0, t; }"
        : "=r"(a) : "l"(p));
    return a;
}

DEVI void cp16(uint32_t dst, const void* src) {
    asm volatile("cp.async.cg.shared.global [%0], [%1], 16;"
                 :: "r"(dst), "l"(src));
}
#define CP_COMMIT() asm volatile("cp.async.commit_group;" ::: "memory")
#define CP_WAIT1()  asm volatile("cp.async.wait_group 1;" ::: "memory")

DEVI void ldsm4(uint32_t r[4], uint32_t addr) {
    asm volatile("ldmatrix.sync.aligned.m8n8.x4.shared.b16 {%0,%1,%2,%3}, [%4];"
                 : "=r"(r[0]), "=r"(r[1]), "=r"(r[2]), "=r"(r[3]) : "r"(addr));
}

DEVI void mma_h(float c[4], const uint32_t a[4], const uint32_t b[2]) {
    asm volatile(
        "mma.sync.aligned.m16n8k16.row.col.f32.f16.f16.f32 "
        "{%0,%1,%2,%3}, {%4,%5,%6,%7}, {%8,%9}, {%0,%1,%2,%3};\n"
        : "+f"(c[0]), "+f"(c[1]), "+f"(c[2]), "+f"(c[3])
        : "r"(a[0]), "r"(a[1]), "r"(a[2]), "r"(a[3]), "r"(b[0]), "r"(b[1]));
}

DEVI uint32_t packh2(float a, float b) {
    __half2 h = __floats2half2_rn(a, b);
    return *reinterpret_cast<uint32_t*>(&h);
}

// ---------------------------------------------------------------------------
// fp16 GEMM: C[M,N] = act( A[M,K] @ Bt[N,K]^T + bias + resid )
// BM=128, BN=128, BK=64, 3-stage cp.async pipeline (R12 ordering) plus
// explicit register double-buffering of ldsm fragments across kk steps.
// 128 threads = 4 warps, warp tile 64x64 (2x2 grid).
// ---------------------------------------------------------------------------
constexpr int HG_AB  = 128 * 128;          // 16 KB per A stage
constexpr int HG_STG = 2 * HG_AB;          // 32 KB per stage (A + B)
constexpr int HG_SMEM = 3 * HG_STG;        // 96 KB

template <bool RELU>
__global__ void __launch_bounds__(128)
hgemm(const __half* __restrict__ A, const __half* __restrict__ Bt,
      const float* __restrict__ bias, const float* __restrict__ resid,
      float* __restrict__ Cf, __half* __restrict__ Ch, int K, int N)
{
    extern __shared__ __align__(16) char smem[];
    const uint32_t dsb = s2u(smem);

    const int m0 = blockIdx.y * 128;
    const int n0 = blockIdx.x * 128;
    const int tid = threadIdx.x, lane = tid & 31, warp = tid >> 5;
    const int wm = (warp >> 1) * 64;
    const int wn = (warp & 1) * 64;

    const __half* ga = A  + (long long)m0 * K;
    const __half* gb = Bt + (long long)n0 * K;

    auto issue = [&](int t, int st) {
        const uint32_t sa = dsb + st * HG_STG;
        const uint32_t sb = sa + HG_AB;
        const __half* pa = ga + t * 64;
        const __half* pb = gb + t * 64;
#pragma unroll
        for (int i = 0; i < 8; i++) {
            const int idx = tid + i * 128;
            const int r = idx >> 3, c = idx & 7;
            const uint32_t sw = (uint32_t)(r * 128 + ((c ^ (r & 7)) << 4));
            cp16(sa + sw, pa + (long long)r * K + c * 8);
            cp16(sb + sw, pb + (long long)r * K + c * 8);
        }
    };

    float acc[4][8][4];
#pragma unroll
    for (int mt = 0; mt < 4; mt++)
#pragma unroll
        for (int nt = 0; nt < 8; nt++)
#pragma unroll
            for (int i = 0; i < 4; i++) acc[mt][nt][i] = 0.f;

    const int T = K / 64;
    issue(0, 0); CP_COMMIT();
    issue(1, 1); CP_COMMIT();

    const int arow = lane & 15;
    const int akh  = lane >> 4;
    const int brow = ((lane >> 4) << 3) + (lane & 7);
    const int bkh  = (lane >> 3) & 1;

    // fragment loader for one kk step
    auto ld_frags = [&](uint32_t sa, uint32_t sb, int kk,
                        uint32_t af[4][4], uint32_t bf[8][2]) {
#pragma unroll
        for (int mt = 0; mt < 4; mt++) {
            const int r = wm + mt * 16 + arow;
            const int c = kk * 2 + akh;
            ldsm4(af[mt], sa + r * 128 + ((c ^ (r & 7)) << 4));
        }
#pragma unroll
        for (int bt = 0; bt < 4; bt++) {
            const int r = wn + bt * 16 + brow;
            const int c = kk * 2 + bkh;
            uint32_t qq[4];
            ldsm4(qq, sb + r * 128 + ((c ^ (r & 7)) << 4));
            bf[2 * bt][0] = qq[0]; bf[2 * bt][1] = qq[1];
            bf[2 * bt + 1][0] = qq[2]; bf[2 * bt + 1][1] = qq[3];
        }
    };

    for (int t = 0; t < T; t++) {
        CP_WAIT1();
        __syncthreads();
        const uint32_t sa = dsb + (t % 3) * HG_STG;
        const uint32_t sb = sa + HG_AB;

        uint32_t af[2][4][4];
        uint32_t bf[2][8][2];
        ld_frags(sa, sb, 0, af[0], bf[0]);
#pragma unroll
        for (int kk = 0; kk < 4; kk++) {
            const int cur = kk & 1, nxt = cur ^ 1;
            if (kk < 3) ld_frags(sa, sb, kk + 1, af[nxt], bf[nxt]);
#pragma unroll
            for (int mt = 0; mt < 4; mt++)
#pragma unroll
                for (int nt = 0; nt < 8; nt++)
                    mma_h(acc[mt][nt], af[cur][mt], bf[cur][nt]);
        }

        const int tn = t + 2;
        if (tn < T) issue(tn, tn % 3);
        CP_COMMIT();
    }

#pragma unroll
    for (int mt = 0; mt < 4; mt++) {
#pragma unroll
        for (int nt = 0; nt < 8; nt++) {
            const int col = n0 + wn + nt * 8 + 2 * (lane & 3);
#pragma unroll
            for (int h = 0; h < 2; h++) {
                const int row = m0 + wm + mt * 16 + (lane >> 2) + h * 8;
                float v0 = acc[mt][nt][2 * h];
                float v1 = acc[mt][nt][2 * h + 1];
                if (bias)  { v0 += bias[col]; v1 += bias[col + 1]; }
                if (resid) {
                    const float* rp = resid + (long long)row * N + col;
                    v0 += rp[0]; v1 += rp[1];
                }
                if (RELU) { v0 = fmaxf(v0, 0.f); v1 = fmaxf(v1, 0.f); }
                const long long o = (long long)row * N + col;
                if (Cf) *reinterpret_cast<float2*>(Cf + o) = make_float2(v0, v1);
                if (Ch) *reinterpret_cast<__half2*>(Ch + o) = __floats2half2_rn(v0, v1);
            }
        }
    }
}

// ---------------------------------------------------------------------------
// Fused flash attention over fused QKV buffer [B*S, 3072].  (R12 version)
//   q cols [0,1024), k cols [1024,2048); head h at +h*64.
//   vt: [bh][64][512]; ctx out: [B*S, 1024].
// ---------------------------------------------------------------------------
constexpr int FA_QB  = 16384;
constexpr int FA_KB  = 16384;
constexpr int FA_VB  = 16384;
constexpr int FA_KVB = FA_KB + FA_VB;
constexpr int FA_SMEM = FA_QB + 3 * FA_KVB;   // 112 KB

__global__ void __launch_bounds__(256)
flash_attn(const __half* __restrict__ qkv, const __half* __restrict__ vt,
           __half* __restrict__ ctx)
{
    extern __shared__ __align__(16) char smem[];
    const uint32_t sQ = s2u(smem);
    const uint32_t sKV0 = sQ + FA_QB;

    const int bh = blockIdx.y, b = bh >> 4, h = bh & 15;
    const int q0 = blockIdx.x * 128;
    const int tid = threadIdx.x, lane = tid & 31, warp = tid >> 5;

    const __half* gq = qkv + ((long long)(b * 512 + q0)) * 3072 + h * 64;
    const __half* gk = qkv + ((long long)(b * 512)) * 3072 + 1024 + h * 64;
    const __half* gv = vt + (long long)bh * 64 * 512;

#pragma unroll
    for (int i = 0; i < 4; i++) {
        const int idx = tid + i * 256;
        const int r = idx >> 3, c = idx & 7;
        cp16(sQ + r * 128 + ((c ^ (r & 7)) << 4), gq + (long long)r * 3072 + c * 8);
    }
    auto ldKV = [&](int t, int st) {
        const uint32_t sk = sKV0 + st * FA_KVB;
        const uint32_t sv = sk + FA_KB;
        const __half* pk = gk + (long long)t * 128 * 3072;
#pragma unroll
        for (int i = 0; i < 4; i++) {
            const int idx = tid + i * 256;
            const int r = idx >> 3, c = idx & 7;
            cp16(sk + r * 128 + ((c ^ (r & 7)) << 4), pk + (long long)r * 3072 + c * 8);
        }
#pragma unroll
        for (int i = 0; i < 4; i++) {
            const int idx = tid + i * 256;
            const int r = idx >> 4, c = idx & 15;
            cp16(sv + r * 256 + ((c ^ (r & 7)) << 4),
                 gv + (long long)r * 512 + t * 128 + c * 8);
        }
    };
    ldKV(0, 0); CP_COMMIT();
    ldKV(1, 1); CP_COMMIT();

    // scale folds 1/sqrt(d) and log2(e): softmax in exp2 domain (fp32)
    const float SC = 0.125f * 1.44269504f;

    float m0v = -1e30f, m1v = -1e30f, l0 = 0.f, l1 = 0.f;
    float oa[8][4];
#pragma unroll
    for (int nt = 0; nt < 8; nt++)
#pragma unroll
        for (int i = 0; i < 4; i++) oa[nt][i] = 0.f;

    const int arow = lane & 15, akh = lane >> 4;
    const int brow = ((lane >> 4) << 3) + (lane & 7), bkh = (lane >> 3) & 1;

    uint32_t afq[4][4];      // Q fragments, loaded once at t==0

    for (int t = 0; t < 4; t++) {
        CP_WAIT1();
        __syncthreads();
        const uint32_t sk = sKV0 + (t % 3) * FA_KVB;
        const uint32_t sv = sk + FA_KB;

        if (t == 0) {
#pragma unroll
            for (int kk = 0; kk < 4; kk++) {
                const int r = warp * 16 + arow;
                const int c = kk * 2 + akh;
                ldsm4(afq[kk], sQ + r * 128 + ((c ^ (r & 7)) << 4));
            }
        }

        // ---- S = Q @ K^T (warp: 16 q-rows x 128 kv-cols) ----
        float sacc[16][4];
#pragma unroll
        for (int nt = 0; nt < 16; nt++)
#pragma unroll
            for (int i = 0; i < 4; i++) sacc[nt][i] = 0.f;
#pragma unroll
        for (int kk = 0; kk < 4; kk++) {
            uint32_t bf[16][2];
#pragma unroll
            for (int bt = 0; bt < 8; bt++) {
                const int r = bt * 16 + brow;
                const int c = kk * 2 + bkh;
                uint32_t qq[4];
                ldsm4(qq, sk + r * 128 + ((c ^ (r & 7)) << 4));
                bf[2 * bt][0] = qq[0]; bf[2 * bt][1] = qq[1];
                bf[2 * bt + 1][0] = qq[2]; bf[2 * bt + 1][1] = qq[3];
            }
#pragma unroll
            for (int nt = 0; nt < 16; nt++)
                mma_h(sacc[nt], afq[kk], bf[nt]);
        }

        // ---- online softmax, exp2 domain (rows lane>>2 and +8) ----
        float mx0 = -1e30f, mx1 = -1e30f;
#pragma unroll
        for (int nt = 0; nt < 16; nt++) {
            sacc[nt][0] *= SC; sacc[nt][1] *= SC;
            sacc[nt][2] *= SC; sacc[nt][3] *= SC;
            mx0 = fmaxf(mx0, fmaxf(sacc[nt][0], sacc[nt][1]));
            mx1 = fmaxf(mx1, fmaxf(sacc[nt][2], sacc[nt][3]));
        }
        mx0 = fmaxf(mx0, __shfl_xor_sync(0xffffffffu, mx0, 1));
        mx0 = fmaxf(mx0, __shfl_xor_sync(0xffffffffu, mx0, 2));
        mx1 = fmaxf(mx1, __shfl_xor_sync(0xffffffffu, mx1, 1));
        mx1 = fmaxf(mx1, __shfl_xor_sync(0xffffffffu, mx1, 2));
        const float mn0 = fmaxf(m0v, mx0), mn1 = fmaxf(m1v, mx1);
        const float al0 = exp2f(m0v - mn0), al1 = exp2f(m1v - mn1);

        uint32_t ph[16][2];
        float s0 = 0.f, s1 = 0.f;
#pragma unroll
        for (int nt = 0; nt < 16; nt++) {
            const float e0 = exp2f(sacc[nt][0] - mn0);
            const float e1 = exp2f(sacc[nt][1] - mn0);
            const float e2 = exp2f(sacc[nt][2] - mn1);
            const float e3 = exp2f(sacc[nt][3] - mn1);
            s0 += e0 + e1; s1 += e2 + e3;
            ph[nt][0] = packh2(e0, e1);
            ph[nt][1] = packh2(e2, e3);
        }
        s0 += __shfl_xor_sync(0xffffffffu, s0, 1);
        s0 += __shfl_xor_sync(0xffffffffu, s0, 2);
        s1 += __shfl_xor_sync(0xffffffffu, s1, 1);
        s1 += __shfl_xor_sync(0xffffffffu, s1, 2);
        l0 = al0 * l0 + s0; l1 = al1 * l1 + s1;
#pragma unroll
        for (int nt = 0; nt < 8; nt++) {
            oa[nt][0] *= al0; oa[nt][1] *= al0;
            oa[nt][2] *= al1; oa[nt][3] *= al1;
        }
        m0v = mn0; m1v = mn1;

        // ---- O += P @ V^T-tile ----
#pragma unroll
        for (int kc = 0; kc < 8; kc++) {
            uint32_t a[4] = {ph[2 * kc][0], ph[2 * kc][1],
                             ph[2 * kc + 1][0], ph[2 * kc + 1][1]};
            uint32_t bv[8][2];
#pragma unroll
            for (int bt = 0; bt < 4; bt++) {
                const int r = bt * 16 + brow;
                const int c = kc * 2 + bkh;
                uint32_t qq[4];
                ldsm4(qq, sv + r * 256 + ((c ^ (r & 7)) << 4));
                bv[2 * bt][0] = qq[0]; bv[2 * bt][1] = qq[1];
                bv[2 * bt + 1][0] = qq[2]; bv[2 * bt + 1][1] = qq[3];
            }
#pragma unroll
            for (int nt = 0; nt < 8; nt++)
                mma_h(oa[nt], a, bv[nt]);
        }

        const int tn = t + 2;
        if (tn < 4) ldKV(tn, tn % 3);
        CP_COMMIT();
    }

    const float r0 = 1.f / l0, r1 = 1.f / l1;
    const int row_lo = b * 512 + q0 + warp * 16 + (lane >> 2);
    __half* c0p = ctx + (long long)row_lo * 1024 + h * 64 + 2 * (lane & 3);
    __half* c1p = c0p + 8 * 1024;
#pragma unroll
    for (int nt = 0; nt < 8; nt++) {
        *reinterpret_cast<__half2*>(c0p + nt * 8) =
            __floats2half2_rn(oa[nt][0] * r0, oa[nt][1] * r0);
        *reinterpret_cast<__half2*>(c1p + nt * 8) =
            __floats2half2_rn(oa[nt][2] * r1, oa[nt][3] * r1);
    }
}

// ---------------------------------------------------------------------------
// Square weights -> f16 transposed. z = m*4 + l; m in {0,1,2}=QKV interleaved,
// m=3 -> Wp region.
// ---------------------------------------------------------------------------
__global__ void __launch_bounds__(256)
transpose_sq(const float* __restrict__ a0, const float* __restrict__ a1,
             const float* __restrict__ a2, const float* __restrict__ a3,
             __half* __restrict__ wt)
{
    __shared__ float tile[32][33];
    const int m = blockIdx.z >> 2, l = blockIdx.z & 3;
    const float* src = (m == 0 ? a0 : m == 1 ? a1 : m == 2 ? a2 : a3)
                       + (long long)l * 1048576;
    __half* dst = (m < 3)
        ? wt + ((long long)l * 3 + m) * 1048576
        : wt + WT_P + (long long)l * 1048576;
    const int c0 = blockIdx.x * 32, r0 = blockIdx.y * 32;
    const int tx = threadIdx.x & 31, ty = threadIdx.x >> 5;
#pragma unroll
    for (int i = 0; i < 4; i++)
        tile[ty + 8 * i][tx] = src[(long long)(r0 + ty + 8 * i) * 1024 + c0 + tx];
    __syncthreads();
#pragma unroll
    for (int i = 0; i < 4; i++)
        dst[(long long)(c0 + ty + 8 * i) * 1024 + r0 + tx] =
            __float2half(tile[tx][ty + 8 * i]);
}

// ---------------------------------------------------------------------------
// Generic weight transpose [R,C] f32 -> [C,R] f16 (grid.z = layer)
// ---------------------------------------------------------------------------
__global__ void __launch_bounds__(256)
transpose_wh(const float* __restrict__ src, __half* __restrict__ dst, int R, int Cn)
{
    __shared__ float tile[32][33];
    const long long msz = (long long)R * Cn;
    src += blockIdx.z * msz; dst += blockIdx.z * msz;
    const int c0 = blockIdx.x * 32, r0 = blockIdx.y * 32;
    const int tx = threadIdx.x & 31, ty = threadIdx.x >> 5;
#pragma unroll
    for (int i = 0; i < 4; i++)
        tile[ty + 8 * i][tx] = src[(long long)(r0 + ty + 8 * i) * Cn + c0 + tx];
    __syncthreads();
#pragma unroll
    for (int i = 0; i < 4; i++)
        dst[(long long)(c0 + ty + 8 * i) * R + r0 + tx] =
            __float2half(tile[tx][ty + 8 * i]);
}

// ---------------------------------------------------------------------------
// Bias concat: bqkv[l][3072] = [bq | bk | bv]
// ---------------------------------------------------------------------------
__global__ void __launch_bounds__(256)
concat_bias(const float* __restrict__ bq, const float* __restrict__ bk,
            const float* __restrict__ bv, float* __restrict__ out)
{
    const int i = blockIdx.x * 256 + threadIdx.x;      // 0 .. 12287
    const int l = i / 3072, j = i % 3072;
    float v;
    if (j < 1024)       v = bq[l * 1024 + j];
    else if (j < 2048)  v = bk[l * 1024 + j - 1024];
    else                v = bv[l * 1024 + j - 2048];
    out[i] = v;
}

// ---------------------------------------------------------------------------
// Per-head V transpose from fused qkv: vt[bh][64][512]
// ---------------------------------------------------------------------------
__global__ void __launch_bounds__(256)
transpose_v(const __half* __restrict__ qkv, __half* __restrict__ vt)
{
    __shared__ __half tile[64][65];
    const int s0 = blockIdx.x * 64;
    const int bh = blockIdx.y;
    const int b = bh >> 4, h = bh & 15;
    const int tid = threadIdx.x;
    const __half* v = qkv + 2048 + h * 64;
#pragma unroll
    for (int i = 0; i < 16; i++) {
        const int lin = tid + i * 256;
        const int r = lin >> 6, c = lin & 63;
        tile[c][r] = v[((long long)(b * 512 + s0 + r)) * 3072 + c];
    }
    __syncthreads();
    __half* dst = vt + (long long)bh * 64 * 512;
#pragma unroll
    for (int i = 0; i < 16; i++) {
        const int lin = tid + i * 256;
        const int r = lin >> 6, c = lin & 63;
        dst[(long long)r * 512 + s0 + c] = tile[r][c];
    }
}

// ---------------------------------------------------------------------------
// f32 copy + f16 convert
// ---------------------------------------------------------------------------
__global__ void __launch_bounds__(256)
cvtcopy(const float* __restrict__ src, float* __restrict__ dst,
        __half* __restrict__ dsth, int n)
{
    const int i = (blockIdx.x * 256 + threadIdx.x) * 4;
    if (i < n) {
        float4 v = *reinterpret_cast<const float4*>(src + i);
        *reinterpret_cast<float4*>(dst + i) = v;
        *reinterpret_cast<__half2*>(dsth + i)     = __floats2half2_rn(v.x, v.y);
        *reinterpret_cast<__half2*>(dsth + i + 2) = __floats2half2_rn(v.z, v.w);
    }
}

// ---------------------------------------------------------------------------
// LayerNorm over D=1024, dual f32 + f16 outputs, float4 access.
// ---------------------------------------------------------------------------
__global__ void __launch_bounds__(256)
ln1024(const float* __restrict__ x, const float* __restrict__ g,
       const float* __restrict__ be, float* __restrict__ out,
       __half* __restrict__ out16)
{
    __shared__ float red[16];
    const int row = blockIdx.x, tid = threadIdx.x;
    const float4 v4 = *reinterpret_cast<const float4*>(x + (long long)row * 1024 + tid * 4);
    float s  = v4.x + v4.y + v4.z + v4.w;
    float sq = v4.x * v4.x + v4.y * v4.y + v4.z * v4.z + v4.w * v4.w;
    const int lane = tid & 31, w = tid >> 5;
#pragma unroll
    for (int o = 16; o > 0; o >>= 1) {
        s  += __shfl_xor_sync(0xffffffffu, s, o);
        sq += __shfl_xor_sync(0xffffffffu, sq, o);
    }
    if (lane == 0) { red[w] = s; red[8 + w] = sq; }
    __syncthreads();
    s = 0.f; sq = 0.f;
#pragma unroll
    for (int i = 0; i < 8; i++) { s += red[i]; sq += red[8 + i]; }
    const float mean = s * (1.f / 1024.f);
    const float var  = sq * (1.f / 1024.f) - mean * mean;
    const float inv  = rsqrtf(var + 1e-6f);
    const float4 g4  = *reinterpret_cast<const float4*>(g  + tid * 4);
    const float4 b4  = *reinterpret_cast<const float4*>(be + tid * 4);
    float4 o4;
    o4.x = (v4.x - mean) * inv * g4.x + b4.x;
    o4.y = (v4.y - mean) * inv * g4.y + b4.y;
    o4.z = (v4.z - mean) * inv * g4.z + b4.z;
    o4.w = (v4.w - mean) * inv * g4.w + b4.w;
    *reinterpret_cast<float4*>(out + (long long)row * 1024 + tid * 4) = o4;
    __half* o16 = out16 + (long long)row * 1024 + tid * 4;
    *reinterpret_cast<__half2*>(o16)     = __floats2half2_rn(o4.x, o4.y);
    *reinterpret_cast<__half2*>(o16 + 2) = __floats2half2_rn(o4.z, o4.w);
}

// ---------------------------------------------------------------------------
// Driver
// ---------------------------------------------------------------------------
extern "C" void kernel_launch(void* const* d_in, const int* in_sizes, int n_in,
                              void* d_out, int out_size)
{
    using namespace cfg;
    (void)in_sizes; (void)n_in; (void)out_size;

    const float* hs  = (const float*)d_in[0];
    const float* Wq  = (const float*)d_in[1];
    const float* bq  = (const float*)d_in[2];
    const float* Wk  = (const float*)d_in[3];
    const float* bk  = (const float*)d_in[4];
    const float* Wv  = (const float*)d_in[5];
    const float* bv  = (const float*)d_in[6];
    const float* Wp  = (const float*)d_in[7];
    const float* bp  = (const float*)d_in[8];
    const float* g1  = (const float*)d_in[9];
    const float* be1 = (const float*)d_in[10];
    const float* W1  = (const float*)d_in[11];
    const float* b1  = (const float*)d_in[12];
    const float* W2  = (const float*)d_in[13];
    const float* b2  = (const float*)d_in[14];
    const float* g2  = (const float*)d_in[15];
    const float* be2 = (const float*)d_in[16];

    float* x = (float*)d_out;

    float *t0, *x1, *bqkv;
    __half *x16, *x116, *qkv16, *vt, *ctx16, *hh16, *wt;
    cudaGetSymbolAddress((void**)&t0,    g_t0);
    cudaGetSymbolAddress((void**)&x1,    g_x1);
    cudaGetSymbolAddress((void**)&bqkv,  g_bqkv);
    cudaGetSymbolAddress((void**)&x16,   h_x);
    cudaGetSymbolAddress((void**)&x116,  h_x1b);
    cudaGetSymbolAddress((void**)&qkv16, h_qkv);
    cudaGetSymbolAddress((void**)&vt,    h_vt);
    cudaGetSymbolAddress((void**)&ctx16, h_ctx);
    cudaGetSymbolAddress((void**)&hh16,  h_hh);
    cudaGetSymbolAddress((void**)&wt,    h_wt);

    cudaFuncSetAttribute(hgemm<false>, cudaFuncAttributeMaxDynamicSharedMemorySize, HG_SMEM);
    cudaFuncSetAttribute(hgemm<true>,  cudaFuncAttributeMaxDynamicSharedMemorySize, HG_SMEM);
    cudaFuncSetAttribute(flash_attn,   cudaFuncAttributeMaxDynamicSharedMemorySize, FA_SMEM);

    const dim3 blk(256);
    const dim3 blkg(128);

    // 3 prep launches -> first (fused QKV) hgemm is launch index 3, the
    // slot ncu captures.
    transpose_sq<<<dim3(32, 32, 16), blk>>>(Wq, Wk, Wv, Wp, wt);
    concat_bias<<<48, blk>>>(bq, bk, bv, bqkv);
    cvtcopy<<<NM * ND / 1024, blk>>>(hs, x, x16, NM * ND);

    bool w12_done = false;

    for (int l = 0; l < NL; l++) {
        const __half* wqkv = wt + WT_QKV + (long long)l * 3 * 1048576;
        const __half* wtp  = wt + WT_P   + (long long)l * ND * ND;
        const __half* wt1  = wt + WT_1   + (long long)l * ND * NF;
        const __half* wt2  = wt + WT_2   + (long long)l * NF * ND;
        const float* bqkvl = bqkv + (long long)l * 3 * ND;
        const float* bpl = bp + (long long)l * ND;
        const float* b1l = b1 + (long long)l * NF;
        const float* b2l = b2 + (long long)l * ND;
        const float* g1l = g1 + (long long)l * ND;
        const float* e1l = be1 + (long long)l * ND;
        const float* g2l = g2 + (long long)l * ND;
        const float* e2l = be2 + (long long)l * ND;

        // fused QKV: [8192, 3072]
        hgemm<false><<<dim3(24, 64), blkg, HG_SMEM>>>(
            x16, wqkv, bqkvl, nullptr, nullptr, qkv16, ND, 3 * ND);

        if (!w12_done) {
            transpose_wh<<<dim3(128, 32, NL), blk>>>(W1, wt + WT_1, ND, NF);
            transpose_wh<<<dim3(32, 128, NL), blk>>>(W2, wt + WT_2, NF, ND);
            w12_done = true;
        }

        transpose_v<<<dim3(8, NB * NH), blk>>>(qkv16, vt);

        flash_attn<<<dim3(4, NB * NH), blk, FA_SMEM>>>(qkv16, vt, ctx16);

        hgemm<false><<<dim3(8, 64), blkg, HG_SMEM>>>(
            ctx16, wtp, bpl, x, t0, nullptr, ND, ND);

        ln1024<<<NM, blk>>>(t0, g1l, e1l, x1, x116);

        hgemm<true><<<dim3(32, 64), blkg, HG_SMEM>>>(
            x116, wt1, b1l, nullptr, nullptr, hh16, ND, NF);

        hgemm<false><<<dim3(8, 64), blkg, HG_SMEM>>>(
            hh16, wt2, b2l, x1, t0, nullptr, NF, ND);

        ln1024<<<NM, blk>>>(t0, g2l, e2l, x, x16);
    }
}